// round 13
// baseline (speedup 1.0000x reference)
#include <cuda_runtime.h>
#include <cuda_bf16.h>
#include <math_constants.h>
#include <float.h>

// VectorQuantizer: N=32768 rows, D=256, K=4096.
// bf16 mma.sync filter (certified margin, argmax-dot form) + exact fp32
// rescore. Exact chain (verified rel_err=0.0 R1-R9):
//   dist = fl( fl(A_r + B_k) - fl(2 * dot_seq_fma(x_r,c_k)) ), argmin lowest
//   index on ties.
// R13: tcgen05 unavailable (toolchain targets compute_100). R9 skeleton +
//  (a) argmax-dot epilogue: B-norm (<=256*cmax^2 ~ 1e-8) folded into margin;
//      no B loads, no shared rowmin/atomics in the k-loop;
//  (b) explicit double-buffered ldsm fragments (2-stage sw pipeline);
//  (c) fused prep (c+x) and fused rescore+output+loss kernels.

#define VQ_N 32768
#define VQ_D 256
#define VQ_K 4096

#define GM   256  // rows per CTA
#define GN   64   // codewords per tile
#define NT   (VQ_K / GN)
#define NBUF 3
#define CAP  256
#define GT   512
#define XWB  512  // bytes per smem row (256 bf16, unpadded)
#define CBUF (GN * XWB)            // 32768 B per c buffer
#define XBYTES (GM * XWB)          // 131072 B x tile

__device__ __nv_bfloat16 g_xh[VQ_N * VQ_D];
__device__ __nv_bfloat16 g_ch[VQ_K * VQ_D];
__device__ float    g_A[VQ_N];
__device__ float    g_S1[VQ_N];
__device__ float    g_B[VQ_K];
__device__ unsigned g_cmaxbits;
__device__ int      g_candCnt[VQ_N];
__device__ int      g_cand[VQ_N * CAP];
__device__ double   g_losssum;

// ---------------------------------------------------------------- helpers
__device__ __forceinline__ unsigned smem_u32(const void* p) {
    return (unsigned)__cvta_generic_to_shared(p);
}
__device__ __forceinline__ void cp16(unsigned dst, const void* src) {
    asm volatile("cp.async.cg.shared.global [%0], [%1], 16;\n" :: "r"(dst), "l"(src));
}
#define CP_COMMIT() asm volatile("cp.async.commit_group;\n")
#define CP_WAIT0()  asm volatile("cp.async.wait_group 0;\n")

__device__ __forceinline__ void mbar_init(unsigned addr, unsigned cnt) {
    asm volatile("mbarrier.init.shared.b64 [%0], %1;\n" :: "r"(addr), "r"(cnt) : "memory");
}
__device__ __forceinline__ void mbar_arrive(unsigned addr) {
    asm volatile("mbarrier.arrive.shared.b64 _, [%0];\n" :: "r"(addr) : "memory");
}
__device__ __forceinline__ void cpasync_arrive_noinc(unsigned addr) {
    asm volatile("cp.async.mbarrier.arrive.noinc.shared.b64 [%0];\n" :: "r"(addr) : "memory");
}
__device__ __forceinline__ void mbar_wait(unsigned addr, unsigned parity) {
    asm volatile(
        "{\n\t.reg .pred P;\n\t"
        "WAIT_%=:\n\t"
        "mbarrier.try_wait.parity.acquire.cta.shared::cta.b64 P, [%0], %1, 0x989680;\n\t"
        "@P bra.uni DONE_%=;\n\t"
        "bra.uni WAIT_%=;\n\t"
        "DONE_%=:\n\t}"
        :: "r"(addr), "r"(parity) : "memory");
}

__device__ __forceinline__ void ldsm4(unsigned* r, unsigned addr) {
    asm volatile("ldmatrix.sync.aligned.m8n8.x4.shared.b16 {%0,%1,%2,%3}, [%4];\n"
                 : "=r"(r[0]), "=r"(r[1]), "=r"(r[2]), "=r"(r[3]) : "r"(addr));
}
__device__ __forceinline__ void mma16816(float c[4], const unsigned* a,
                                         unsigned b0, unsigned b1) {
    asm volatile(
        "mma.sync.aligned.m16n8k16.row.col.f32.bf16.bf16.f32 "
        "{%0,%1,%2,%3}, {%4,%5,%6,%7}, {%8,%9}, {%0,%1,%2,%3};\n"
        : "+f"(c[0]), "+f"(c[1]), "+f"(c[2]), "+f"(c[3])
        : "r"(a[0]), "r"(a[1]), "r"(a[2]), "r"(a[3]), "r"(b0), "r"(b1));
}

// ---------------------------------------------------------------- zero
__global__ void vq_zero_kernel() {
    int i = blockIdx.x * blockDim.x + threadIdx.x;
    if (i < VQ_N) g_candCnt[i] = 0;
    if (i == 0) { g_losssum = 0.0; g_cmaxbits = 0u; }
}

// ---------------------------------------------------------------- fused prep (c: blocks 0-127, x: blocks 128-1151)
__global__ __launch_bounds__(256) void vq_prep(const float* __restrict__ x,
                                               const float* __restrict__ cb) {
    __shared__ float sb[32][257];
    __shared__ float smax[256];
    const int tid = threadIdx.x;
    const bool is_c = (blockIdx.x < 128);
    const int row0 = (is_c ? blockIdx.x : (blockIdx.x - 128)) * 32;
    const float* src = is_c ? cb : x;
    __nv_bfloat16* dsth = is_c ? g_ch : g_xh;
    float m = 0.0f;
#pragma unroll
    for (int it = 0; it < 8; it++) {
        int idx = tid + it * 256;
        int r   = idx >> 6;
        int c4  = idx & 63;
        float4 v = ((const float4*)(src + (size_t)(row0 + r) * VQ_D))[c4];
        sb[r][c4 * 4 + 0] = v.x; sb[r][c4 * 4 + 1] = v.y;
        sb[r][c4 * 4 + 2] = v.z; sb[r][c4 * 4 + 3] = v.w;
        if (is_c)
            m = fmaxf(m, fmaxf(fmaxf(fabsf(v.x), fabsf(v.y)), fmaxf(fabsf(v.z), fabsf(v.w))));
        __nv_bfloat162 p0, p1;
        p0.x = __float2bfloat16(v.x); p0.y = __float2bfloat16(v.y);
        p1.x = __float2bfloat16(v.z); p1.y = __float2bfloat16(v.w);
        __nv_bfloat162* dst = (__nv_bfloat162*)(dsth + (size_t)(row0 + r) * VQ_D);
        dst[c4 * 2] = p0; dst[c4 * 2 + 1] = p1;
    }
    smax[tid] = m;
    __syncthreads();
    if (tid < 32) {
        float s = 0.0f, s1 = 0.0f;
        for (int i = 0; i < VQ_D; i++) {
            float v = sb[tid][i];
            s  = __fadd_rn(s, __fmul_rn(v, v));   // strict sequential ascending
            s1 += fabsf(v);
        }
        if (is_c) {
            g_B[row0 + tid] = s;
        } else {
            g_A[row0 + tid]  = s;
            g_S1[row0 + tid] = s1;
        }
    }
    if (is_c) {
        for (int s = 128; s > 0; s >>= 1) {
            if (tid < s) smax[tid] = fmaxf(smax[tid], smax[tid + s]);
            __syncthreads();
        }
        if (tid == 0) atomicMax(&g_cmaxbits, __float_as_uint(smax[0]));
    }
}

// ---------------------------------------------------------------- gemm + candidate collect
__global__ __launch_bounds__(GT, 1) void vq_gemm_kernel() {
    extern __shared__ unsigned char smem_dyn[];
    unsigned char* xs = smem_dyn;              // XBYTES
    unsigned char* cs = smem_dyn + XBYTES;     // NBUF * CBUF
    __shared__ unsigned long long s_full[NBUF], s_empty[NBUF];

    const int tid  = threadIdx.x;
    const int w    = tid >> 5;
    const int lane = tid & 31;
    const int g    = lane >> 2;
    const int tg   = lane & 3;
    const int rowbase = (w >> 1) * 32;
    const int colbase = (w & 1) * 32;
    const int row0 = blockIdx.x * GM;
    const unsigned xs_b = smem_u32(xs);
    const unsigned cs_b = smem_u32(cs);

    // ldmatrix lane addressing (logical layout = R7/R9, swizzled rows)
    const int j  = lane >> 3;
    const int rl = lane & 7;
    const int a_row  = rowbase + (j & 1) * 8 + rl;
    const unsigned sA = (unsigned)(a_row & 7);
    const unsigned cA = (unsigned)(j >> 1);
    const unsigned xA0 = xs_b + a_row * XWB;
    const unsigned xA1 = xA0 + 16 * XWB;
    const int b_row  = colbase + (j >> 1) * 8 + rl;
    const unsigned sB = (unsigned)(b_row & 7);
    const unsigned cB = (unsigned)(j & 1);
    const unsigned bo0 = (unsigned)(b_row * XWB);
    const unsigned bo1 = bo0 + 16 * XWB;

    // async-copy x tile, swizzled: chunk c (16B) of row r -> (c ^ (r&7))
#pragma unroll
    for (int q = 0; q < 16; q++) {
        int idx = tid + q * GT;
        int r = idx >> 5, c = idx & 31;
        cp16(xs_b + r * XWB + (unsigned)((c ^ (r & 7)) << 4),
             (const uint4*)(g_xh + (size_t)(row0 + r) * VQ_D) + c);
    }
    CP_COMMIT();

    if (tid == 0) {
#pragma unroll
        for (int s = 0; s < NBUF; s++) {
            mbar_init(smem_u32(&s_full[s]), GT);
            mbar_init(smem_u32(&s_empty[s]), GT);
        }
    }

    // per-thread rows + margins (argmax-dot space):
    // thr_dot = 0.5*eps_dist + 0.5*Bmax = 0.0165*cmax*S1 + 2e-4 + 256*cmax^2
    int   lrow[4];
    float accThr[4], runmax[4];
    float cmax = __uint_as_float(g_cmaxbits);
#pragma unroll
    for (int mi = 0; mi < 4; mi++) {
        int lr = rowbase + (mi >> 1) * 16 + (mi & 1) * 8 + g;
        lrow[mi]   = lr;
        accThr[mi] = 0.0165f * cmax * g_S1[row0 + lr] + 2.0e-4f
                   + 256.0f * cmax * cmax;
        runmax[mi] = -FLT_MAX;
    }

    CP_WAIT0();
    __syncthreads();   // x in smem, barriers initialized

    // produce tile 0
    {
        const __nv_bfloat16* src = g_ch;
#pragma unroll
        for (int q = 0; q < 4; q++) {
            int idx = tid + q * GT;
            int r = idx >> 5, c = idx & 31;
            cp16(cs_b + r * XWB + (unsigned)((c ^ (r & 7)) << 4),
                 (const uint4*)(src + (size_t)r * VQ_D) + c);
        }
        cpasync_arrive_noinc(smem_u32(&s_full[0]));
    }

    for (int t = 0; t < NT; t++) {
        // produce tile t+1 before consuming t
        int u = t + 1;
        if (u < NT) {
            int bu = u % NBUF;
            if (u >= NBUF)
                mbar_wait(smem_u32(&s_empty[bu]), (unsigned)((u / NBUF - 1) & 1));
            const __nv_bfloat16* src = g_ch + (size_t)u * GN * VQ_D;
            unsigned base = cs_b + bu * CBUF;
#pragma unroll
            for (int q = 0; q < 4; q++) {
                int idx = tid + q * GT;
                int r = idx >> 5, c = idx & 31;
                cp16(base + r * XWB + (unsigned)((c ^ (r & 7)) << 4),
                     (const uint4*)(src + (size_t)r * VQ_D) + c);
            }
            cpasync_arrive_noinc(smem_u32(&s_full[bu]));
        }

        const int b = t % NBUF;
        mbar_wait(smem_u32(&s_full[b]), (unsigned)((t / NBUF) & 1));
        const unsigned cur = cs_b + b * CBUF;

        float acc[2][4][4];
#pragma unroll
        for (int mt = 0; mt < 2; mt++)
#pragma unroll
            for (int nt = 0; nt < 4; nt++)
#pragma unroll
                for (int q = 0; q < 4; q++) acc[mt][nt][q] = 0.0f;

        // 2-stage software-pipelined fragments
        unsigned fa0[2][4], fa1[2][4], fb01[2][4], fb23[2][4];
        {
            unsigned tA = (cA ^ sA) << 4;
            unsigned tB = (cB ^ sB) << 4;
            ldsm4(fa0[0], xA0 + tA);
            ldsm4(fa1[0], xA1 + tA);
            ldsm4(fb01[0], cur + bo0 + tB);
            ldsm4(fb23[0], cur + bo1 + tB);
        }
#pragma unroll
        for (int i = 0; i < 16; i++) {
            const int c = i & 1, n = c ^ 1;
            if (i < 15) {
                unsigned tA = (((unsigned)(2 * (i + 1)) + cA) ^ sA) << 4;
                unsigned tB = (((unsigned)(2 * (i + 1)) + cB) ^ sB) << 4;
                ldsm4(fa0[n], xA0 + tA);
                ldsm4(fa1[n], xA1 + tA);
                ldsm4(fb01[n], cur + bo0 + tB);
                ldsm4(fb23[n], cur + bo1 + tB);
            }
            mma16816(acc[0][0], fa0[c], fb01[c][0], fb01[c][1]);
            mma16816(acc[0][1], fa0[c], fb01[c][2], fb01[c][3]);
            mma16816(acc[0][2], fa0[c], fb23[c][0], fb23[c][1]);
            mma16816(acc[0][3], fa0[c], fb23[c][2], fb23[c][3]);
            mma16816(acc[1][0], fa1[c], fb01[c][0], fb01[c][1]);
            mma16816(acc[1][1], fa1[c], fb01[c][2], fb01[c][3]);
            mma16816(acc[1][2], fa1[c], fb23[c][0], fb23[c][1]);
            mma16816(acc[1][3], fa1[c], fb23[c][2], fb23[c][3]);
        }

        // epilogue (argmax-dot): local max, quad-butterfly, private running max
        const int kb = t * GN + colbase;
        float lmax[4] = {-FLT_MAX, -FLT_MAX, -FLT_MAX, -FLT_MAX};
#pragma unroll
        for (int nt = 0; nt < 4; nt++)
#pragma unroll
            for (int mt = 0; mt < 2; mt++) {
                lmax[2 * mt]     = fmaxf(lmax[2 * mt],
                                         fmaxf(acc[mt][nt][0], acc[mt][nt][1]));
                lmax[2 * mt + 1] = fmaxf(lmax[2 * mt + 1],
                                         fmaxf(acc[mt][nt][2], acc[mt][nt][3]));
            }
#pragma unroll
        for (int mi = 0; mi < 4; mi++) {
            lmax[mi] = fmaxf(lmax[mi], __shfl_xor_sync(0xffffffffu, lmax[mi], 1));
            lmax[mi] = fmaxf(lmax[mi], __shfl_xor_sync(0xffffffffu, lmax[mi], 2));
            runmax[mi] = fmaxf(runmax[mi], lmax[mi]);
        }
        float cut[4];
        bool mine = false;
#pragma unroll
        for (int mi = 0; mi < 4; mi++) cut[mi] = runmax[mi] - accThr[mi];
#pragma unroll
        for (int nt = 0; nt < 4; nt++)
#pragma unroll
            for (int mt = 0; mt < 2; mt++)
#pragma unroll
                for (int q = 0; q < 4; q++)
                    mine |= (acc[mt][nt][q] > cut[2 * mt + (q >> 1)]);

        if (__ballot_sync(0xffffffffu, mine)) {
#pragma unroll
            for (int nt = 0; nt < 4; nt++) {
                int kA = kb + nt * 8 + 2 * tg;
#pragma unroll
                for (int mt = 0; mt < 2; mt++) {
#pragma unroll
                    for (int q = 0; q < 4; q++) {
                        int mi = 2 * mt + (q >> 1);
                        if (acc[mt][nt][q] > cut[mi]) {
                            int grow = row0 + lrow[mi];
                            int pos = atomicAdd(&g_candCnt[grow], 1);
                            if (pos < CAP) g_cand[grow * CAP + pos] = kA + (q & 1);
                        }
                    }
                }
            }
        }

        mbar_arrive(smem_u32(&s_empty[b]));
    }
}

// ---------------------------------------------------------------- fused exact rescore + output + loss
__device__ __forceinline__ float exact_dist(const float* __restrict__ xr,
                                            const float* __restrict__ ck,
                                            float Ar, float Bk) {
    float acc = 0.0f;
    const float4* x4 = (const float4*)xr;
    const float4* c4 = (const float4*)ck;
#pragma unroll 4
    for (int i = 0; i < VQ_D / 4; i++) {
        float4 a = __ldg(x4 + i);
        float4 b = __ldg(c4 + i);
        acc = __fmaf_rn(a.x, b.x, acc);
        acc = __fmaf_rn(a.y, b.y, acc);
        acc = __fmaf_rn(a.z, b.z, acc);
        acc = __fmaf_rn(a.w, b.w, acc);
    }
    float t  = __fadd_rn(Ar, Bk);
    float m2 = __fmul_rn(2.0f, acc);
    return __fsub_rn(t, m2);
}

__global__ __launch_bounds__(256) void vq_rescore_out(const float* __restrict__ x,
                                                      const float* __restrict__ cb,
                                                      float* __restrict__ out) {
    __shared__ double sls[8];
    const int wrp  = threadIdx.x >> 5;
    const int lane = threadIdx.x & 31;
    const int row  = blockIdx.x * 8 + wrp;
    const int cnt  = g_candCnt[row];
    const float* xr = x + (size_t)row * VQ_D;
    const float  Ar = g_A[row];

    float best = FLT_MAX;
    int   besti = 0x7fffffff;
    if (cnt <= CAP) {
        for (int jc = lane; jc < cnt; jc += 32) {
            int k = g_cand[row * CAP + jc];
            float d = exact_dist(xr, cb + (size_t)k * VQ_D, Ar, g_B[k]);
            if (d < best || (d == best && k < besti)) { best = d; besti = k; }
        }
    } else {
        for (int k = lane; k < VQ_K; k += 32) {
            float d = exact_dist(xr, cb + (size_t)k * VQ_D, Ar, g_B[k]);
            if (d < best || (d == best && k < besti)) { best = d; besti = k; }
        }
    }
#pragma unroll
    for (int off = 16; off > 0; off >>= 1) {
        float v = __shfl_down_sync(0xffffffffu, best, off);
        int   i = __shfl_down_sync(0xffffffffu, besti, off);
        if (v < best || (v == best && i < besti)) { best = v; besti = i; }
    }
    besti = __shfl_sync(0xffffffffu, besti, 0);

    // output row + loss partials (exact ops preserved)
    const float4* x4 = (const float4*)xr;
    const float4* q4 = (const float4*)(cb + (size_t)besti * VQ_D);
    float4* o4 = (float4*)(out + (size_t)row * VQ_D);
    double ls = 0.0;
#pragma unroll
    for (int h = 0; h < 2; h++) {
        int i4 = lane + h * 32;
        float4 xv = x4[i4];
        float4 qv = q4[i4];
        float d0 = __fsub_rn(qv.x, xv.x);
        float d1 = __fsub_rn(qv.y, xv.y);
        float d2 = __fsub_rn(qv.z, xv.z);
        float d3 = __fsub_rn(qv.w, xv.w);
        float4 ov;
        ov.x = __fadd_rn(xv.x, d0);
        ov.y = __fadd_rn(xv.y, d1);
        ov.z = __fadd_rn(xv.z, d2);
        ov.w = __fadd_rn(xv.w, d3);
        o4[i4] = ov;
        ls += (double)__fmul_rn(d0, d0) + (double)__fmul_rn(d1, d1)
            + (double)__fmul_rn(d2, d2) + (double)__fmul_rn(d3, d3);
    }
#pragma unroll
    for (int off = 16; off > 0; off >>= 1)
        ls += __shfl_down_sync(0xffffffffu, ls, off);
    if (lane == 0) sls[wrp] = ls;
    __syncthreads();
    if (threadIdx.x == 0) {
        double s = 0.0;
#pragma unroll
        for (int i = 0; i < 8; i++) s += sls[i];
        atomicAdd(&g_losssum, s);
    }
}

// ---------------------------------------------------------------- finalize loss
__global__ void vq_finalize_kernel(float* __restrict__ out, int has_loss) {
    if (!has_loss) return;
    float m = (float)(g_losssum * (1.0 / (double)(VQ_N * VQ_D)));
    float commit = __fmul_rn(m, 0.25f);
    out[VQ_N * VQ_D] = __fadd_rn(commit, m);
}

// ---------------------------------------------------------------- launch
extern "C" void kernel_launch(void* const* d_in, const int* in_sizes, int n_in,
                              void* d_out, int out_size)
{
    const float* latents  = (const float*)d_in[0];
    const float* codebook = (const float*)d_in[1];
    if (n_in >= 2 && in_sizes[0] == VQ_K * VQ_D && in_sizes[1] == VQ_N * VQ_D) {
        latents  = (const float*)d_in[1];
        codebook = (const float*)d_in[0];
    }
    float* out = (float*)d_out;
    int has_loss = (out_size > VQ_N * VQ_D) ? 1 : 0;

    const int GEMM_SMEM = XBYTES + NBUF * CBUF;   // 229376 bytes
    cudaFuncSetAttribute(vq_gemm_kernel,
                         cudaFuncAttributeMaxDynamicSharedMemorySize, GEMM_SMEM);

    vq_zero_kernel<<<VQ_N / 256, 256>>>();
    vq_prep<<<128 + VQ_N / 32, 256>>>(latents, codebook);
    vq_gemm_kernel<<<VQ_N / GM, GT, GEMM_SMEM>>>();
    vq_rescore_out<<<VQ_N / 8, 256>>>(latents, codebook, out);
    vq_finalize_kernel<<<1, 1>>>(out, has_loss);
}

// round 14
// speedup vs baseline: 1.8334x; 1.8334x over previous
#include <cuda_runtime.h>
#include <cuda_fp16.h>
#include <math_constants.h>
#include <float.h>

// VectorQuantizer: N=32768 rows, D=256, K=4096.
// fp16 mma.sync filter (certified margin, argmax-dot form, c scaled by 2^20)
// + exact fp32 rescore. Exact chain (verified rel_err=0.0 R1-R13):
//   dist = fl( fl(A_r + B_k) - fl(2 * dot_seq_fma(x_r,c_k)) ), argmin lowest
//   index on ties.
// R14: bf16 -> fp16 filter (same MMA rate, rel err 2^-11 vs 2^-8 per operand)
// with codebook pre-scaled by 2^20 (exact pow2, avoids fp16 subnormals).
// Margin 2e ~ 1e-4 (was 1e-3) -> candidates/row ~5 (was ~150); rescore L1
// traffic collapses. Pooled stale row-max restored (shared atomicMax on
// order-preserving uint keys).

#define VQ_N 32768
#define VQ_D 256
#define VQ_K 4096

#define GM   256  // rows per CTA
#define GN   64   // codewords per tile
#define NT   (VQ_K / GN)
#define NBUF 3
#define CAP  256
#define GT   512
#define XWB  512  // bytes per smem row (256 fp16, unpadded)
#define CBUF (GN * XWB)            // 32768 B per c buffer
#define XBYTES (GM * XWB)          // 131072 B x tile
#define SCALE_C 1048576.0f         // 2^20

__device__ __half  g_xh[VQ_N * VQ_D];
__device__ __half  g_ch[VQ_K * VQ_D];   // scaled by 2^20
__device__ float    g_A[VQ_N];
__device__ float    g_S1[VQ_N];
__device__ float    g_B[VQ_K];
__device__ unsigned g_cmaxbits;
__device__ int      g_candCnt[VQ_N];
__device__ int      g_cand[VQ_N * CAP];
__device__ double   g_losssum;

// ---------------------------------------------------------------- helpers
__device__ __forceinline__ unsigned smem_u32(const void* p) {
    return (unsigned)__cvta_generic_to_shared(p);
}
__device__ __forceinline__ void cp16(unsigned dst, const void* src) {
    asm volatile("cp.async.cg.shared.global [%0], [%1], 16;\n" :: "r"(dst), "l"(src));
}
#define CP_COMMIT() asm volatile("cp.async.commit_group;\n")
#define CP_WAIT0()  asm volatile("cp.async.wait_group 0;\n")

__device__ __forceinline__ void mbar_init(unsigned addr, unsigned cnt) {
    asm volatile("mbarrier.init.shared.b64 [%0], %1;\n" :: "r"(addr), "r"(cnt) : "memory");
}
__device__ __forceinline__ void mbar_arrive(unsigned addr) {
    asm volatile("mbarrier.arrive.shared.b64 _, [%0];\n" :: "r"(addr) : "memory");
}
__device__ __forceinline__ void cpasync_arrive_noinc(unsigned addr) {
    asm volatile("cp.async.mbarrier.arrive.noinc.shared.b64 [%0];\n" :: "r"(addr) : "memory");
}
__device__ __forceinline__ void mbar_wait(unsigned addr, unsigned parity) {
    asm volatile(
        "{\n\t.reg .pred P;\n\t"
        "WAIT_%=:\n\t"
        "mbarrier.try_wait.parity.acquire.cta.shared::cta.b64 P, [%0], %1, 0x989680;\n\t"
        "@P bra.uni DONE_%=;\n\t"
        "bra.uni WAIT_%=;\n\t"
        "DONE_%=:\n\t}"
        :: "r"(addr), "r"(parity) : "memory");
}

__device__ __forceinline__ void ldsm4(unsigned* r, unsigned addr) {
    asm volatile("ldmatrix.sync.aligned.m8n8.x4.shared.b16 {%0,%1,%2,%3}, [%4];\n"
                 : "=r"(r[0]), "=r"(r[1]), "=r"(r[2]), "=r"(r[3]) : "r"(addr));
}
__device__ __forceinline__ void mma16816(float c[4], const unsigned* a,
                                         unsigned b0, unsigned b1) {
    asm volatile(
        "mma.sync.aligned.m16n8k16.row.col.f32.f16.f16.f32 "
        "{%0,%1,%2,%3}, {%4,%5,%6,%7}, {%8,%9}, {%0,%1,%2,%3};\n"
        : "+f"(c[0]), "+f"(c[1]), "+f"(c[2]), "+f"(c[3])
        : "r"(a[0]), "r"(a[1]), "r"(a[2]), "r"(a[3]), "r"(b0), "r"(b1));
}

// order-preserving float<->uint for shared atomicMax (handles negatives)
__device__ __forceinline__ unsigned fkey(float f) {
    unsigned b = __float_as_uint(f);
    return (b & 0x80000000u) ? ~b : (b | 0x80000000u);
}
__device__ __forceinline__ float fval(unsigned k) {
    return __uint_as_float((k & 0x80000000u) ? (k ^ 0x80000000u) : ~k);
}

// ---------------------------------------------------------------- zero
__global__ void vq_zero_kernel() {
    int i = blockIdx.x * blockDim.x + threadIdx.x;
    if (i < VQ_N) g_candCnt[i] = 0;
    if (i == 0) { g_losssum = 0.0; g_cmaxbits = 0u; }
}

// ---------------------------------------------------------------- fused prep (c: blocks 0-127, x: blocks 128-1151)
__global__ __launch_bounds__(256) void vq_prep(const float* __restrict__ x,
                                               const float* __restrict__ cb) {
    __shared__ float sb[32][257];
    __shared__ float smax[256];
    const int tid = threadIdx.x;
    const bool is_c = (blockIdx.x < 128);
    const int row0 = (is_c ? blockIdx.x : (blockIdx.x - 128)) * 32;
    const float* src = is_c ? cb : x;
    __half* dsth = is_c ? g_ch : g_xh;
    const float scale = is_c ? SCALE_C : 1.0f;
    float m = 0.0f;
#pragma unroll
    for (int it = 0; it < 8; it++) {
        int idx = tid + it * 256;
        int r   = idx >> 6;
        int c4  = idx & 63;
        float4 v = ((const float4*)(src + (size_t)(row0 + r) * VQ_D))[c4];
        sb[r][c4 * 4 + 0] = v.x; sb[r][c4 * 4 + 1] = v.y;
        sb[r][c4 * 4 + 2] = v.z; sb[r][c4 * 4 + 3] = v.w;
        if (is_c)
            m = fmaxf(m, fmaxf(fmaxf(fabsf(v.x), fabsf(v.y)), fmaxf(fabsf(v.z), fabsf(v.w))));
        __half2 p0, p1;
        p0.x = __float2half_rn(v.x * scale); p0.y = __float2half_rn(v.y * scale);
        p1.x = __float2half_rn(v.z * scale); p1.y = __float2half_rn(v.w * scale);
        __half2* dst = (__half2*)(dsth + (size_t)(row0 + r) * VQ_D);
        dst[c4 * 2] = p0; dst[c4 * 2 + 1] = p1;
    }
    smax[tid] = m;
    __syncthreads();
    if (tid < 32) {
        float s = 0.0f, s1 = 0.0f;
        for (int i = 0; i < VQ_D; i++) {
            float v = sb[tid][i];
            s  = __fadd_rn(s, __fmul_rn(v, v));   // strict sequential ascending
            s1 += fabsf(v);
        }
        if (is_c) {
            g_B[row0 + tid] = s;
        } else {
            g_A[row0 + tid]  = s;
            g_S1[row0 + tid] = s1;
        }
    }
    if (is_c) {
        for (int s = 128; s > 0; s >>= 1) {
            if (tid < s) smax[tid] = fmaxf(smax[tid], smax[tid + s]);
            __syncthreads();
        }
        if (tid == 0) atomicMax(&g_cmaxbits, __float_as_uint(smax[0]));
    }
}

// ---------------------------------------------------------------- gemm + candidate collect
__global__ __launch_bounds__(GT, 1) void vq_gemm_kernel() {
    extern __shared__ unsigned char smem_dyn[];
    unsigned char* xs = smem_dyn;              // XBYTES
    unsigned char* cs = smem_dyn + XBYTES;     // NBUF * CBUF
    __shared__ unsigned long long s_full[NBUF], s_empty[NBUF];
    __shared__ unsigned s_rowmax[GM];

    const int tid  = threadIdx.x;
    const int w    = tid >> 5;
    const int lane = tid & 31;
    const int g    = lane >> 2;
    const int tg   = lane & 3;
    const int rowbase = (w >> 1) * 32;
    const int colbase = (w & 1) * 32;
    const int row0 = blockIdx.x * GM;
    const unsigned xs_b = smem_u32(xs);
    const unsigned cs_b = smem_u32(cs);

    // ldmatrix lane addressing (logical layout = R9/R13, swizzled rows)
    const int j  = lane >> 3;
    const int rl = lane & 7;
    const int a_row  = rowbase + (j & 1) * 8 + rl;
    const unsigned sA = (unsigned)(a_row & 7);
    const unsigned cA = (unsigned)(j >> 1);
    const unsigned xA0 = xs_b + a_row * XWB;
    const unsigned xA1 = xA0 + 16 * XWB;
    const int b_row  = colbase + (j >> 1) * 8 + rl;
    const unsigned sB = (unsigned)(b_row & 7);
    const unsigned cB = (unsigned)(j & 1);
    const unsigned bo0 = (unsigned)(b_row * XWB);
    const unsigned bo1 = bo0 + 16 * XWB;

    // async-copy x tile, swizzled: chunk c (16B) of row r -> (c ^ (r&7))
#pragma unroll
    for (int q = 0; q < 16; q++) {
        int idx = tid + q * GT;
        int r = idx >> 5, c = idx & 31;
        cp16(xs_b + r * XWB + (unsigned)((c ^ (r & 7)) << 4),
             (const uint4*)(g_xh + (size_t)(row0 + r) * VQ_D) + c);
    }
    CP_COMMIT();

    if (tid < GM) s_rowmax[tid] = 0u;   // key-space -inf
    if (tid == 0) {
#pragma unroll
        for (int s = 0; s < NBUF; s++) {
            mbar_init(smem_u32(&s_full[s]), GT);
            mbar_init(smem_u32(&s_empty[s]), GT);
        }
    }

    // per-thread rows + margins (scaled argmax-dot space):
    // thr_dot = 2e + slack = 0.002*cmax*S1 + 2e-4 ; scaled by 2^20
    int   lrow[4];
    float accThr[4], runmax[4];
    float cmax = __uint_as_float(g_cmaxbits);
#pragma unroll
    for (int mi = 0; mi < 4; mi++) {
        int lr = rowbase + (mi >> 1) * 16 + (mi & 1) * 8 + g;
        lrow[mi]   = lr;
        accThr[mi] = (0.002f * cmax * g_S1[row0 + lr] + 2.0e-4f) * SCALE_C;
        runmax[mi] = -FLT_MAX;
    }

    CP_WAIT0();
    __syncthreads();   // x in smem, barriers + rowmax initialized

    // produce tile 0
    {
        const __half* src = g_ch;
#pragma unroll
        for (int q = 0; q < 4; q++) {
            int idx = tid + q * GT;
            int r = idx >> 5, c = idx & 31;
            cp16(cs_b + r * XWB + (unsigned)((c ^ (r & 7)) << 4),
                 (const uint4*)(src + (size_t)r * VQ_D) + c);
        }
        cpasync_arrive_noinc(smem_u32(&s_full[0]));
    }

    for (int t = 0; t < NT; t++) {
        // produce tile t+1 before consuming t
        int u = t + 1;
        if (u < NT) {
            int bu = u % NBUF;
            if (u >= NBUF)
                mbar_wait(smem_u32(&s_empty[bu]), (unsigned)((u / NBUF - 1) & 1));
            const __half* src = g_ch + (size_t)u * GN * VQ_D;
            unsigned base = cs_b + bu * CBUF;
#pragma unroll
            for (int q = 0; q < 4; q++) {
                int idx = tid + q * GT;
                int r = idx >> 5, c = idx & 31;
                cp16(base + r * XWB + (unsigned)((c ^ (r & 7)) << 4),
                     (const uint4*)(src + (size_t)r * VQ_D) + c);
            }
            cpasync_arrive_noinc(smem_u32(&s_full[bu]));
        }

        const int b = t % NBUF;
        mbar_wait(smem_u32(&s_full[b]), (unsigned)((t / NBUF) & 1));
        const unsigned cur = cs_b + b * CBUF;

        float acc[2][4][4];
#pragma unroll
        for (int mt = 0; mt < 2; mt++)
#pragma unroll
            for (int nt = 0; nt < 4; nt++)
#pragma unroll
                for (int q = 0; q < 4; q++) acc[mt][nt][q] = 0.0f;

        // 2-stage software-pipelined fragments
        unsigned fa0[2][4], fa1[2][4], fb01[2][4], fb23[2][4];
        {
            unsigned tA = (cA ^ sA) << 4;
            unsigned tB = (cB ^ sB) << 4;
            ldsm4(fa0[0], xA0 + tA);
            ldsm4(fa1[0], xA1 + tA);
            ldsm4(fb01[0], cur + bo0 + tB);
            ldsm4(fb23[0], cur + bo1 + tB);
        }
#pragma unroll
        for (int i = 0; i < 16; i++) {
            const int c = i & 1, n = c ^ 1;
            if (i < 15) {
                unsigned tA = (((unsigned)(2 * (i + 1)) + cA) ^ sA) << 4;
                unsigned tB = (((unsigned)(2 * (i + 1)) + cB) ^ sB) << 4;
                ldsm4(fa0[n], xA0 + tA);
                ldsm4(fa1[n], xA1 + tA);
                ldsm4(fb01[n], cur + bo0 + tB);
                ldsm4(fb23[n], cur + bo1 + tB);
            }
            mma16816(acc[0][0], fa0[c], fb01[c][0], fb01[c][1]);
            mma16816(acc[0][1], fa0[c], fb01[c][2], fb01[c][3]);
            mma16816(acc[0][2], fa0[c], fb23[c][0], fb23[c][1]);
            mma16816(acc[0][3], fa0[c], fb23[c][2], fb23[c][3]);
            mma16816(acc[1][0], fa1[c], fb01[c][0], fb01[c][1]);
            mma16816(acc[1][1], fa1[c], fb01[c][2], fb01[c][3]);
            mma16816(acc[1][2], fa1[c], fb23[c][0], fb23[c][1]);
            mma16816(acc[1][3], fa1[c], fb23[c][2], fb23[c][3]);
        }

        // epilogue: local max, quad-butterfly, pooled stale shared max
        const int kb = t * GN + colbase;
        float lmax[4] = {-FLT_MAX, -FLT_MAX, -FLT_MAX, -FLT_MAX};
#pragma unroll
        for (int nt = 0; nt < 4; nt++)
#pragma unroll
            for (int mt = 0; mt < 2; mt++) {
                lmax[2 * mt]     = fmaxf(lmax[2 * mt],
                                         fmaxf(acc[mt][nt][0], acc[mt][nt][1]));
                lmax[2 * mt + 1] = fmaxf(lmax[2 * mt + 1],
                                         fmaxf(acc[mt][nt][2], acc[mt][nt][3]));
            }
        float cut[4];
        bool mine = false;
#pragma unroll
        for (int mi = 0; mi < 4; mi++) {
            lmax[mi] = fmaxf(lmax[mi], __shfl_xor_sync(0xffffffffu, lmax[mi], 1));
            lmax[mi] = fmaxf(lmax[mi], __shfl_xor_sync(0xffffffffu, lmax[mi], 2));
            runmax[mi] = fmaxf(runmax[mi], lmax[mi]);
            float pooled = fval(s_rowmax[lrow[mi]]);   // stale: other warp / prev tiles
            cut[mi] = fmaxf(pooled, runmax[mi]) - accThr[mi];
            if (tg == 0)
                atomicMax(&s_rowmax[lrow[mi]], fkey(runmax[mi]));
        }
#pragma unroll
        for (int nt = 0; nt < 4; nt++)
#pragma unroll
            for (int mt = 0; mt < 2; mt++)
#pragma unroll
                for (int q = 0; q < 4; q++)
                    mine |= (acc[mt][nt][q] > cut[2 * mt + (q >> 1)]);

        if (__ballot_sync(0xffffffffu, mine)) {
#pragma unroll
            for (int nt = 0; nt < 4; nt++) {
                int kA = kb + nt * 8 + 2 * tg;
#pragma unroll
                for (int mt = 0; mt < 2; mt++) {
#pragma unroll
                    for (int q = 0; q < 4; q++) {
                        int mi = 2 * mt + (q >> 1);
                        if (acc[mt][nt][q] > cut[mi]) {
                            int grow = row0 + lrow[mi];
                            int pos = atomicAdd(&g_candCnt[grow], 1);
                            if (pos < CAP) g_cand[grow * CAP + pos] = kA + (q & 1);
                        }
                    }
                }
            }
        }

        mbar_arrive(smem_u32(&s_empty[b]));
    }
}

// ---------------------------------------------------------------- fused exact rescore + output + loss
__device__ __forceinline__ float exact_dist(const float* __restrict__ xr,
                                            const float* __restrict__ ck,
                                            float Ar, float Bk) {
    float acc = 0.0f;
    const float4* x4 = (const float4*)xr;
    const float4* c4 = (const float4*)ck;
#pragma unroll 4
    for (int i = 0; i < VQ_D / 4; i++) {
        float4 a = __ldg(x4 + i);
        float4 b = __ldg(c4 + i);
        acc = __fmaf_rn(a.x, b.x, acc);
        acc = __fmaf_rn(a.y, b.y, acc);
        acc = __fmaf_rn(a.z, b.z, acc);
        acc = __fmaf_rn(a.w, b.w, acc);
    }
    float t  = __fadd_rn(Ar, Bk);
    float m2 = __fmul_rn(2.0f, acc);
    return __fsub_rn(t, m2);
}

__global__ __launch_bounds__(256) void vq_rescore_out(const float* __restrict__ x,
                                                      const float* __restrict__ cb,
                                                      float* __restrict__ out) {
    __shared__ double sls[8];
    const int wrp  = threadIdx.x >> 5;
    const int lane = threadIdx.x & 31;
    const int row  = blockIdx.x * 8 + wrp;
    const int cnt  = g_candCnt[row];
    const float* xr = x + (size_t)row * VQ_D;
    const float  Ar = g_A[row];

    float best = FLT_MAX;
    int   besti = 0x7fffffff;
    if (cnt <= CAP) {
        for (int jc = lane; jc < cnt; jc += 32) {
            int k = g_cand[row * CAP + jc];
            float d = exact_dist(xr, cb + (size_t)k * VQ_D, Ar, g_B[k]);
            if (d < best || (d == best && k < besti)) { best = d; besti = k; }
        }
    } else {
        for (int k = lane; k < VQ_K; k += 32) {
            float d = exact_dist(xr, cb + (size_t)k * VQ_D, Ar, g_B[k]);
            if (d < best || (d == best && k < besti)) { best = d; besti = k; }
        }
    }
#pragma unroll
    for (int off = 16; off > 0; off >>= 1) {
        float v = __shfl_down_sync(0xffffffffu, best, off);
        int   i = __shfl_down_sync(0xffffffffu, besti, off);
        if (v < best || (v == best && i < besti)) { best = v; besti = i; }
    }
    besti = __shfl_sync(0xffffffffu, besti, 0);

    // output row + loss partials (exact ops preserved)
    const float4* x4 = (const float4*)xr;
    const float4* q4 = (const float4*)(cb + (size_t)besti * VQ_D);
    float4* o4 = (float4*)(out + (size_t)row * VQ_D);
    double ls = 0.0;
#pragma unroll
    for (int h = 0; h < 2; h++) {
        int i4 = lane + h * 32;
        float4 xv = x4[i4];
        float4 qv = q4[i4];
        float d0 = __fsub_rn(qv.x, xv.x);
        float d1 = __fsub_rn(qv.y, xv.y);
        float d2 = __fsub_rn(qv.z, xv.z);
        float d3 = __fsub_rn(qv.w, xv.w);
        float4 ov;
        ov.x = __fadd_rn(xv.x, d0);
        ov.y = __fadd_rn(xv.y, d1);
        ov.z = __fadd_rn(xv.z, d2);
        ov.w = __fadd_rn(xv.w, d3);
        o4[i4] = ov;
        ls += (double)__fmul_rn(d0, d0) + (double)__fmul_rn(d1, d1)
            + (double)__fmul_rn(d2, d2) + (double)__fmul_rn(d3, d3);
    }
#pragma unroll
    for (int off = 16; off > 0; off >>= 1)
        ls += __shfl_down_sync(0xffffffffu, ls, off);
    if (lane == 0) sls[wrp] = ls;
    __syncthreads();
    if (threadIdx.x == 0) {
        double s = 0.0;
#pragma unroll
        for (int i = 0; i < 8; i++) s += sls[i];
        atomicAdd(&g_losssum, s);
    }
}

// ---------------------------------------------------------------- finalize loss
__global__ void vq_finalize_kernel(float* __restrict__ out, int has_loss) {
    if (!has_loss) return;
    float m = (float)(g_losssum * (1.0 / (double)(VQ_N * VQ_D)));
    float commit = __fmul_rn(m, 0.25f);
    out[VQ_N * VQ_D] = __fadd_rn(commit, m);
}

// ---------------------------------------------------------------- launch
extern "C" void kernel_launch(void* const* d_in, const int* in_sizes, int n_in,
                              void* d_out, int out_size)
{
    const float* latents  = (const float*)d_in[0];
    const float* codebook = (const float*)d_in[1];
    if (n_in >= 2 && in_sizes[0] == VQ_K * VQ_D && in_sizes[1] == VQ_N * VQ_D) {
        latents  = (const float*)d_in[1];
        codebook = (const float*)d_in[0];
    }
    float* out = (float*)d_out;
    int has_loss = (out_size > VQ_N * VQ_D) ? 1 : 0;

    const int GEMM_SMEM = XBYTES + NBUF * CBUF;   // 229376 bytes
    cudaFuncSetAttribute(vq_gemm_kernel,
                         cudaFuncAttributeMaxDynamicSharedMemorySize, GEMM_SMEM);

    vq_zero_kernel<<<VQ_N / 256, 256>>>();
    vq_prep<<<128 + VQ_N / 32, 256>>>(latents, codebook);
    vq_gemm_kernel<<<VQ_N / GM, GT, GEMM_SMEM>>>();
    vq_rescore_out<<<VQ_N / 8, 256>>>(latents, codebook, out);
    vq_finalize_kernel<<<1, 1>>>(out, has_loss);
}

// round 15
// speedup vs baseline: 1.8622x; 1.0157x over previous
#include <cuda_runtime.h>
#include <cuda_fp16.h>
#include <math_constants.h>
#include <float.h>

// VectorQuantizer: N=32768 rows, D=256, K=4096.
// fp16 mma.sync filter (certified margin, argmax-dot, c scaled 2^20) + exact
// fp32 rescore. Exact chain (verified rel_err=0.0 R1-R14):
//   dist = fl( fl(A_r + B_k) - fl(2 * dot_seq_fma(x_r,c_k)) ), argmin lowest
//   index on ties.
// R15: rescore de-divergence — candidate codebook rows staged into padded
// smem via coalesced warp loads (codebook is L2-resident), serial bit-exact
// dot then reads smem. Removes the ~8x L1 wavefront amplification seen in
// R14 (L1=71% on a 0.3GB logical gather). Gemm/prep/margins unchanged.

#define VQ_N 32768
#define VQ_D 256
#define VQ_K 4096

#define GM   256  // rows per CTA
#define GN   64   // codewords per tile
#define NT   (VQ_K / GN)
#define NBUF 3
#define CAP  256
#define GT   512
#define XWB  512  // bytes per smem row (256 fp16, unpadded)
#define CBUF (GN * XWB)            // 32768 B per c buffer
#define XBYTES (GM * XWB)          // 131072 B x tile
#define SCALE_C 1048576.0f         // 2^20

#define RPAD 260                   // staged row pitch (floats)
#define RCHUNK 8                   // candidates staged per chunk
#define RSM_PER_WARP ((RCHUNK + 1) * RPAD)          // 8 cand rows + x row
#define RSM_SMEM (8 * RSM_PER_WARP * 4)             // 74880 B

__device__ __half  g_xh[VQ_N * VQ_D];
__device__ __half  g_ch[VQ_K * VQ_D];   // scaled by 2^20
__device__ float    g_A[VQ_N];
__device__ float    g_S1[VQ_N];
__device__ float    g_B[VQ_K];
__device__ unsigned g_cmaxbits;
__device__ int      g_candCnt[VQ_N];
__device__ int      g_cand[VQ_N * CAP];
__device__ double   g_losssum;

// ---------------------------------------------------------------- helpers
__device__ __forceinline__ unsigned smem_u32(const void* p) {
    return (unsigned)__cvta_generic_to_shared(p);
}
__device__ __forceinline__ void cp16(unsigned dst, const void* src) {
    asm volatile("cp.async.cg.shared.global [%0], [%1], 16;\n" :: "r"(dst), "l"(src));
}
#define CP_COMMIT() asm volatile("cp.async.commit_group;\n")
#define CP_WAIT0()  asm volatile("cp.async.wait_group 0;\n")

__device__ __forceinline__ void mbar_init(unsigned addr, unsigned cnt) {
    asm volatile("mbarrier.init.shared.b64 [%0], %1;\n" :: "r"(addr), "r"(cnt) : "memory");
}
__device__ __forceinline__ void mbar_arrive(unsigned addr) {
    asm volatile("mbarrier.arrive.shared.b64 _, [%0];\n" :: "r"(addr) : "memory");
}
__device__ __forceinline__ void cpasync_arrive_noinc(unsigned addr) {
    asm volatile("cp.async.mbarrier.arrive.noinc.shared.b64 [%0];\n" :: "r"(addr) : "memory");
}
__device__ __forceinline__ void mbar_wait(unsigned addr, unsigned parity) {
    asm volatile(
        "{\n\t.reg .pred P;\n\t"
        "WAIT_%=:\n\t"
        "mbarrier.try_wait.parity.acquire.cta.shared::cta.b64 P, [%0], %1, 0x989680;\n\t"
        "@P bra.uni DONE_%=;\n\t"
        "bra.uni WAIT_%=;\n\t"
        "DONE_%=:\n\t}"
        :: "r"(addr), "r"(parity) : "memory");
}

__device__ __forceinline__ void ldsm4(unsigned* r, unsigned addr) {
    asm volatile("ldmatrix.sync.aligned.m8n8.x4.shared.b16 {%0,%1,%2,%3}, [%4];\n"
                 : "=r"(r[0]), "=r"(r[1]), "=r"(r[2]), "=r"(r[3]) : "r"(addr));
}
__device__ __forceinline__ void mma16816(float c[4], const unsigned* a,
                                         unsigned b0, unsigned b1) {
    asm volatile(
        "mma.sync.aligned.m16n8k16.row.col.f32.f16.f16.f32 "
        "{%0,%1,%2,%3}, {%4,%5,%6,%7}, {%8,%9}, {%0,%1,%2,%3};\n"
        : "+f"(c[0]), "+f"(c[1]), "+f"(c[2]), "+f"(c[3])
        : "r"(a[0]), "r"(a[1]), "r"(a[2]), "r"(a[3]), "r"(b0), "r"(b1));
}

// order-preserving float<->uint for shared atomicMax (handles negatives)
__device__ __forceinline__ unsigned fkey(float f) {
    unsigned b = __float_as_uint(f);
    return (b & 0x80000000u) ? ~b : (b | 0x80000000u);
}
__device__ __forceinline__ float fval(unsigned k) {
    return __uint_as_float((k & 0x80000000u) ? (k ^ 0x80000000u) : ~k);
}

// ---------------------------------------------------------------- zero
__global__ void vq_zero_kernel() {
    int i = blockIdx.x * blockDim.x + threadIdx.x;
    if (i < VQ_N) g_candCnt[i] = 0;
    if (i == 0) { g_losssum = 0.0; g_cmaxbits = 0u; }
}

// ---------------------------------------------------------------- fused prep (c: blocks 0-127, x: blocks 128-1151)
__global__ __launch_bounds__(256) void vq_prep(const float* __restrict__ x,
                                               const float* __restrict__ cb) {
    __shared__ float sb[32][257];
    __shared__ float smax[256];
    const int tid = threadIdx.x;
    const bool is_c = (blockIdx.x < 128);
    const int row0 = (is_c ? blockIdx.x : (blockIdx.x - 128)) * 32;
    const float* src = is_c ? cb : x;
    __half* dsth = is_c ? g_ch : g_xh;
    const float scale = is_c ? SCALE_C : 1.0f;
    float m = 0.0f;
#pragma unroll
    for (int it = 0; it < 8; it++) {
        int idx = tid + it * 256;
        int r   = idx >> 6;
        int c4  = idx & 63;
        float4 v = ((const float4*)(src + (size_t)(row0 + r) * VQ_D))[c4];
        sb[r][c4 * 4 + 0] = v.x; sb[r][c4 * 4 + 1] = v.y;
        sb[r][c4 * 4 + 2] = v.z; sb[r][c4 * 4 + 3] = v.w;
        if (is_c)
            m = fmaxf(m, fmaxf(fmaxf(fabsf(v.x), fabsf(v.y)), fmaxf(fabsf(v.z), fabsf(v.w))));
        __half2 p0, p1;
        p0.x = __float2half_rn(v.x * scale); p0.y = __float2half_rn(v.y * scale);
        p1.x = __float2half_rn(v.z * scale); p1.y = __float2half_rn(v.w * scale);
        __half2* dst = (__half2*)(dsth + (size_t)(row0 + r) * VQ_D);
        dst[c4 * 2] = p0; dst[c4 * 2 + 1] = p1;
    }
    smax[tid] = m;
    __syncthreads();
    if (tid < 32) {
        float s = 0.0f, s1 = 0.0f;
        for (int i = 0; i < VQ_D; i++) {
            float v = sb[tid][i];
            s  = __fadd_rn(s, __fmul_rn(v, v));   // strict sequential ascending
            s1 += fabsf(v);
        }
        if (is_c) {
            g_B[row0 + tid] = s;
        } else {
            g_A[row0 + tid]  = s;
            g_S1[row0 + tid] = s1;
        }
    }
    if (is_c) {
        for (int s = 128; s > 0; s >>= 1) {
            if (tid < s) smax[tid] = fmaxf(smax[tid], smax[tid + s]);
            __syncthreads();
        }
        if (tid == 0) atomicMax(&g_cmaxbits, __float_as_uint(smax[0]));
    }
}

// ---------------------------------------------------------------- gemm + candidate collect (unchanged from R14)
__global__ __launch_bounds__(GT, 1) void vq_gemm_kernel() {
    extern __shared__ unsigned char smem_dyn[];
    unsigned char* xs = smem_dyn;              // XBYTES
    unsigned char* cs = smem_dyn + XBYTES;     // NBUF * CBUF
    __shared__ unsigned long long s_full[NBUF], s_empty[NBUF];
    __shared__ unsigned s_rowmax[GM];

    const int tid  = threadIdx.x;
    const int w    = tid >> 5;
    const int lane = tid & 31;
    const int g    = lane >> 2;
    const int tg   = lane & 3;
    const int rowbase = (w >> 1) * 32;
    const int colbase = (w & 1) * 32;
    const int row0 = blockIdx.x * GM;
    const unsigned xs_b = smem_u32(xs);
    const unsigned cs_b = smem_u32(cs);

    const int j  = lane >> 3;
    const int rl = lane & 7;
    const int a_row  = rowbase + (j & 1) * 8 + rl;
    const unsigned sA = (unsigned)(a_row & 7);
    const unsigned cA = (unsigned)(j >> 1);
    const unsigned xA0 = xs_b + a_row * XWB;
    const unsigned xA1 = xA0 + 16 * XWB;
    const int b_row  = colbase + (j >> 1) * 8 + rl;
    const unsigned sB = (unsigned)(b_row & 7);
    const unsigned cB = (unsigned)(j & 1);
    const unsigned bo0 = (unsigned)(b_row * XWB);
    const unsigned bo1 = bo0 + 16 * XWB;

#pragma unroll
    for (int q = 0; q < 16; q++) {
        int idx = tid + q * GT;
        int r = idx >> 5, c = idx & 31;
        cp16(xs_b + r * XWB + (unsigned)((c ^ (r & 7)) << 4),
             (const uint4*)(g_xh + (size_t)(row0 + r) * VQ_D) + c);
    }
    CP_COMMIT();

    if (tid < GM) s_rowmax[tid] = 0u;
    if (tid == 0) {
#pragma unroll
        for (int s = 0; s < NBUF; s++) {
            mbar_init(smem_u32(&s_full[s]), GT);
            mbar_init(smem_u32(&s_empty[s]), GT);
        }
    }

    int   lrow[4];
    float accThr[4], runmax[4];
    float cmax = __uint_as_float(g_cmaxbits);
#pragma unroll
    for (int mi = 0; mi < 4; mi++) {
        int lr = rowbase + (mi >> 1) * 16 + (mi & 1) * 8 + g;
        lrow[mi]   = lr;
        accThr[mi] = (0.002f * cmax * g_S1[row0 + lr] + 2.0e-4f) * SCALE_C;
        runmax[mi] = -FLT_MAX;
    }

    CP_WAIT0();
    __syncthreads();

    {
        const __half* src = g_ch;
#pragma unroll
        for (int q = 0; q < 4; q++) {
            int idx = tid + q * GT;
            int r = idx >> 5, c = idx & 31;
            cp16(cs_b + r * XWB + (unsigned)((c ^ (r & 7)) << 4),
                 (const uint4*)(src + (size_t)r * VQ_D) + c);
        }
        cpasync_arrive_noinc(smem_u32(&s_full[0]));
    }

    for (int t = 0; t < NT; t++) {
        int u = t + 1;
        if (u < NT) {
            int bu = u % NBUF;
            if (u >= NBUF)
                mbar_wait(smem_u32(&s_empty[bu]), (unsigned)((u / NBUF - 1) & 1));
            const __half* src = g_ch + (size_t)u * GN * VQ_D;
            unsigned base = cs_b + bu * CBUF;
#pragma unroll
            for (int q = 0; q < 4; q++) {
                int idx = tid + q * GT;
                int r = idx >> 5, c = idx & 31;
                cp16(base + r * XWB + (unsigned)((c ^ (r & 7)) << 4),
                     (const uint4*)(src + (size_t)r * VQ_D) + c);
            }
            cpasync_arrive_noinc(smem_u32(&s_full[bu]));
        }

        const int b = t % NBUF;
        mbar_wait(smem_u32(&s_full[b]), (unsigned)((t / NBUF) & 1));
        const unsigned cur = cs_b + b * CBUF;

        float acc[2][4][4];
#pragma unroll
        for (int mt = 0; mt < 2; mt++)
#pragma unroll
            for (int nt = 0; nt < 4; nt++)
#pragma unroll
                for (int q = 0; q < 4; q++) acc[mt][nt][q] = 0.0f;

        unsigned fa0[2][4], fa1[2][4], fb01[2][4], fb23[2][4];
        {
            unsigned tA = (cA ^ sA) << 4;
            unsigned tB = (cB ^ sB) << 4;
            ldsm4(fa0[0], xA0 + tA);
            ldsm4(fa1[0], xA1 + tA);
            ldsm4(fb01[0], cur + bo0 + tB);
            ldsm4(fb23[0], cur + bo1 + tB);
        }
#pragma unroll
        for (int i = 0; i < 16; i++) {
            const int c = i & 1, n = c ^ 1;
            if (i < 15) {
                unsigned tA = (((unsigned)(2 * (i + 1)) + cA) ^ sA) << 4;
                unsigned tB = (((unsigned)(2 * (i + 1)) + cB) ^ sB) << 4;
                ldsm4(fa0[n], xA0 + tA);
                ldsm4(fa1[n], xA1 + tA);
                ldsm4(fb01[n], cur + bo0 + tB);
                ldsm4(fb23[n], cur + bo1 + tB);
            }
            mma16816(acc[0][0], fa0[c], fb01[c][0], fb01[c][1]);
            mma16816(acc[0][1], fa0[c], fb01[c][2], fb01[c][3]);
            mma16816(acc[0][2], fa0[c], fb23[c][0], fb23[c][1]);
            mma16816(acc[0][3], fa0[c], fb23[c][2], fb23[c][3]);
            mma16816(acc[1][0], fa1[c], fb01[c][0], fb01[c][1]);
            mma16816(acc[1][1], fa1[c], fb01[c][2], fb01[c][3]);
            mma16816(acc[1][2], fa1[c], fb23[c][0], fb23[c][1]);
            mma16816(acc[1][3], fa1[c], fb23[c][2], fb23[c][3]);
        }

        const int kb = t * GN + colbase;
        float lmax[4] = {-FLT_MAX, -FLT_MAX, -FLT_MAX, -FLT_MAX};
#pragma unroll
        for (int nt = 0; nt < 4; nt++)
#pragma unroll
            for (int mt = 0; mt < 2; mt++) {
                lmax[2 * mt]     = fmaxf(lmax[2 * mt],
                                         fmaxf(acc[mt][nt][0], acc[mt][nt][1]));
                lmax[2 * mt + 1] = fmaxf(lmax[2 * mt + 1],
                                         fmaxf(acc[mt][nt][2], acc[mt][nt][3]));
            }
        float cut[4];
        bool mine = false;
#pragma unroll
        for (int mi = 0; mi < 4; mi++) {
            lmax[mi] = fmaxf(lmax[mi], __shfl_xor_sync(0xffffffffu, lmax[mi], 1));
            lmax[mi] = fmaxf(lmax[mi], __shfl_xor_sync(0xffffffffu, lmax[mi], 2));
            runmax[mi] = fmaxf(runmax[mi], lmax[mi]);
            float pooled = fval(s_rowmax[lrow[mi]]);
            cut[mi] = fmaxf(pooled, runmax[mi]) - accThr[mi];
            if (tg == 0)
                atomicMax(&s_rowmax[lrow[mi]], fkey(runmax[mi]));
        }
#pragma unroll
        for (int nt = 0; nt < 4; nt++)
#pragma unroll
            for (int mt = 0; mt < 2; mt++)
#pragma unroll
                for (int q = 0; q < 4; q++)
                    mine |= (acc[mt][nt][q] > cut[2 * mt + (q >> 1)]);

        if (__ballot_sync(0xffffffffu, mine)) {
#pragma unroll
            for (int nt = 0; nt < 4; nt++) {
                int kA = kb + nt * 8 + 2 * tg;
#pragma unroll
                for (int mt = 0; mt < 2; mt++) {
#pragma unroll
                    for (int q = 0; q < 4; q++) {
                        int mi = 2 * mt + (q >> 1);
                        if (acc[mt][nt][q] > cut[mi]) {
                            int grow = row0 + lrow[mi];
                            int pos = atomicAdd(&g_candCnt[grow], 1);
                            if (pos < CAP) g_cand[grow * CAP + pos] = kA + (q & 1);
                        }
                    }
                }
            }
        }

        mbar_arrive(smem_u32(&s_empty[b]));
    }
}

// ---------------------------------------------------------------- fused exact rescore + output + loss
__device__ __forceinline__ float exact_dist_g(const float* __restrict__ xr,
                                              const float* __restrict__ ck,
                                              float Ar, float Bk) {
    float acc = 0.0f;
    const float4* x4 = (const float4*)xr;
    const float4* c4 = (const float4*)ck;
#pragma unroll 4
    for (int i = 0; i < VQ_D / 4; i++) {
        float4 a = __ldg(x4 + i);
        float4 b = __ldg(c4 + i);
        acc = __fmaf_rn(a.x, b.x, acc);
        acc = __fmaf_rn(a.y, b.y, acc);
        acc = __fmaf_rn(a.z, b.z, acc);
        acc = __fmaf_rn(a.w, b.w, acc);
    }
    float t  = __fadd_rn(Ar, Bk);
    float m2 = __fmul_rn(2.0f, acc);
    return __fsub_rn(t, m2);
}

__global__ __launch_bounds__(256) void vq_rescore_out(const float* __restrict__ x,
                                                      const float* __restrict__ cb,
                                                      float* __restrict__ out) {
    extern __shared__ float stg[];            // 8 warps * (RCHUNK+1) * RPAD
    __shared__ double sls[8];
    const int wrp  = threadIdx.x >> 5;
    const int lane = threadIdx.x & 31;
    const int row  = blockIdx.x * 8 + wrp;
    const int cnt  = g_candCnt[row];
    const float* xr = x + (size_t)row * VQ_D;
    const float  Ar = g_A[row];
    float* wstg = stg + wrp * RSM_PER_WARP;   // RCHUNK candidate rows
    float* xstg = wstg + RCHUNK * RPAD;       // staged x row

    float best = FLT_MAX;
    int   besti = 0x7fffffff;
    if (cnt <= CAP) {
        // stage x row once (coalesced)
        {
            const float4* x4 = (const float4*)xr;
#pragma unroll
            for (int h = 0; h < 2; h++) {
                int idx = lane + h * 32;
                *(float4*)&xstg[idx * 4] = __ldg(x4 + idx);
            }
        }
        __syncwarp();
        for (int c0 = 0; c0 < cnt; c0 += RCHUNK) {
            int nch = min(RCHUNK, cnt - c0);
            // stage nch candidate rows, coalesced
            for (int rr = 0; rr < nch; rr++) {
                int k = g_cand[row * CAP + c0 + rr];     // broadcast load
                const float4* c4 = (const float4*)(cb + (size_t)k * VQ_D);
#pragma unroll
                for (int h = 0; h < 2; h++) {
                    int idx = lane + h * 32;
                    *(float4*)&wstg[rr * RPAD + idx * 4] = __ldg(c4 + idx);
                }
            }
            __syncwarp();
            if (lane < nch) {
                int k = g_cand[row * CAP + c0 + lane];
                const float* cr = &wstg[lane * RPAD];
                float acc = 0.0f;
                for (int i = 0; i < VQ_D; i++)
                    acc = __fmaf_rn(xstg[i], cr[i], acc);   // same chain, smem operands
                float t  = __fadd_rn(Ar, g_B[k]);
                float m2 = __fmul_rn(2.0f, acc);
                float d  = __fsub_rn(t, m2);
                if (d < best || (d == best && k < besti)) { best = d; besti = k; }
            }
            __syncwarp();
        }
    } else {
        // overflow fallback: full exact scan (rare)
        for (int k = lane; k < VQ_K; k += 32) {
            float d = exact_dist_g(xr, cb + (size_t)k * VQ_D, Ar, g_B[k]);
            if (d < best || (d == best && k < besti)) { best = d; besti = k; }
        }
    }
#pragma unroll
    for (int off = 16; off > 0; off >>= 1) {
        float v = __shfl_down_sync(0xffffffffu, best, off);
        int   i = __shfl_down_sync(0xffffffffu, besti, off);
        if (v < best || (v == best && i < besti)) { best = v; besti = i; }
    }
    besti = __shfl_sync(0xffffffffu, besti, 0);

    // output row + loss partials (exact ops preserved)
    const float4* x4 = (const float4*)xr;
    const float4* q4 = (const float4*)(cb + (size_t)besti * VQ_D);
    float4* o4 = (float4*)(out + (size_t)row * VQ_D);
    double ls = 0.0;
#pragma unroll
    for (int h = 0; h < 2; h++) {
        int i4 = lane + h * 32;
        float4 xv = x4[i4];
        float4 qv = q4[i4];
        float d0 = __fsub_rn(qv.x, xv.x);
        float d1 = __fsub_rn(qv.y, xv.y);
        float d2 = __fsub_rn(qv.z, xv.z);
        float d3 = __fsub_rn(qv.w, xv.w);
        float4 ov;
        ov.x = __fadd_rn(xv.x, d0);
        ov.y = __fadd_rn(xv.y, d1);
        ov.z = __fadd_rn(xv.z, d2);
        ov.w = __fadd_rn(xv.w, d3);
        o4[i4] = ov;
        ls += (double)__fmul_rn(d0, d0) + (double)__fmul_rn(d1, d1)
            + (double)__fmul_rn(d2, d2) + (double)__fmul_rn(d3, d3);
    }
#pragma unroll
    for (int off = 16; off > 0; off >>= 1)
        ls += __shfl_down_sync(0xffffffffu, ls, off);
    if (lane == 0) sls[wrp] = ls;
    __syncthreads();
    if (threadIdx.x == 0) {
        double s = 0.0;
#pragma unroll
        for (int i = 0; i < 8; i++) s += sls[i];
        atomicAdd(&g_losssum, s);
    }
}

// ---------------------------------------------------------------- finalize loss
__global__ void vq_finalize_kernel(float* __restrict__ out, int has_loss) {
    if (!has_loss) return;
    float m = (float)(g_losssum * (1.0 / (double)(VQ_N * VQ_D)));
    float commit = __fmul_rn(m, 0.25f);
    out[VQ_N * VQ_D] = __fadd_rn(commit, m);
}

// ---------------------------------------------------------------- launch
extern "C" void kernel_launch(void* const* d_in, const int* in_sizes, int n_in,
                              void* d_out, int out_size)
{
    const float* latents  = (const float*)d_in[0];
    const float* codebook = (const float*)d_in[1];
    if (n_in >= 2 && in_sizes[0] == VQ_K * VQ_D && in_sizes[1] == VQ_N * VQ_D) {
        latents  = (const float*)d_in[1];
        codebook = (const float*)d_in[0];
    }
    float* out = (float*)d_out;
    int has_loss = (out_size > VQ_N * VQ_D) ? 1 : 0;

    const int GEMM_SMEM = XBYTES + NBUF * CBUF;   // 229376 bytes
    cudaFuncSetAttribute(vq_gemm_kernel,
                         cudaFuncAttributeMaxDynamicSharedMemorySize, GEMM_SMEM);
    cudaFuncSetAttribute(vq_rescore_out,
                         cudaFuncAttributeMaxDynamicSharedMemorySize, RSM_SMEM);

    vq_zero_kernel<<<VQ_N / 256, 256>>>();
    vq_prep<<<128 + VQ_N / 32, 256>>>(latents, codebook);
    vq_gemm_kernel<<<VQ_N / GM, GT, GEMM_SMEM>>>();
    vq_rescore_out<<<VQ_N / 8, 256, RSM_SMEM>>>(latents, codebook, out);
    vq_finalize_kernel<<<1, 1>>>(out, has_loss);
}